// round 10
// baseline (speedup 1.0000x reference)
#include <cuda_runtime.h>
#include <stdint.h>

// TwoHotEmbedding: out[b,s,:] = W[i1[b,s]] + (i1!=i2 ? W[i2[b,s]] : 0)
// i1,i2 [8,4096] int32; W [50257,512] f32; out [8,4096,512] f32.
//
// R10: persistent grid-stride kernel. R2..R9 established the traffic floor
// (~64MB compulsory writes + ~37MB L2-overflow reads) and that cache-policy
// hints are worth ±1us. Remaining waste was schedule-level: 4096 CTAs =
// ~3.5 waves -> wave-transition gaps where DRAM sits idle (DRAM active only
// 60%). Fix: 1184 CTAs (148 SMs x occ 8), each warp loops over ~3-4 tokens
// with next-token index prefetch, keeping continuous memory pressure.
// Loads: plain __ldg (best measured). Stores: .cs (best measured).

static constexpr int NTOK = 8 * 4096;   // 32768 tokens
static constexpr int CHUNKS = 128;      // float4 per row
static constexpr int NBLK  = 148 * 8;   // persistent grid: 1184 CTAs
static constexpr int WARPS = NBLK * 8;  // 9472 resident warps

__global__ void __launch_bounds__(256)
twohot_kernel(const int* __restrict__ i1,
              const int* __restrict__ i2,
              const float4* __restrict__ W,
              float4* __restrict__ out)
{
    const int warp0 = blockIdx.x * (blockDim.x >> 5) + (threadIdx.x >> 5);
    const int lane  = threadIdx.x & 31;

    // Prefetch first token's indices.
    int t = warp0;
    int a = (t < NTOK) ? __ldg(i1 + t) : 0;
    int b = (t < NTOK) ? __ldg(i2 + t) : 0;

    while (t < NTOK) {
        const float4* ra = W + (long long)a * CHUNKS + lane;
        const float4* rb = W + (long long)b * CHUNKS + lane;
        float4* o = out + (long long)t * CHUNKS + lane;

        // 8 independent gathers, front-batched (MLP=8).
        float4 a0 = __ldg(ra + 0);
        float4 a1 = __ldg(ra + 32);
        float4 a2 = __ldg(ra + 64);
        float4 a3 = __ldg(ra + 96);
        float4 b0 = __ldg(rb + 0);
        float4 b1 = __ldg(rb + 32);
        float4 b2 = __ldg(rb + 64);
        float4 b3 = __ldg(rb + 96);

        float m = (a != b) ? 1.0f : 0.0f;   // warp-uniform

        // Prefetch next token's indices while gathers are in flight.
        int tn = t + WARPS;
        if (tn < NTOK) {
            a = __ldg(i1 + tn);
            b = __ldg(i2 + tn);
        }

        a0.x = fmaf(m, b0.x, a0.x); a0.y = fmaf(m, b0.y, a0.y);
        a0.z = fmaf(m, b0.z, a0.z); a0.w = fmaf(m, b0.w, a0.w);
        a1.x = fmaf(m, b1.x, a1.x); a1.y = fmaf(m, b1.y, a1.y);
        a1.z = fmaf(m, b1.z, a1.z); a1.w = fmaf(m, b1.w, a1.w);
        a2.x = fmaf(m, b2.x, a2.x); a2.y = fmaf(m, b2.y, a2.y);
        a2.z = fmaf(m, b2.z, a2.z); a2.w = fmaf(m, b2.w, a2.w);
        a3.x = fmaf(m, b3.x, a3.x); a3.y = fmaf(m, b3.y, a3.y);
        a3.z = fmaf(m, b3.z, a3.z); a3.w = fmaf(m, b3.w, a3.w);

        __stcs(o + 0,  a0);
        __stcs(o + 32, a1);
        __stcs(o + 64, a2);
        __stcs(o + 96, a3);

        t = tn;
    }
}

extern "C" void kernel_launch(void* const* d_in, const int* in_sizes, int n_in,
                              void* d_out, int out_size)
{
    const int*    i1 = (const int*)d_in[0];
    const int*    i2 = (const int*)d_in[1];
    const float4* W  = (const float4*)d_in[2];
    float4*       out = (float4*)d_out;

    twohot_kernel<<<NBLK, 256>>>(i1, i2, W, out);
}